// round 13
// baseline (speedup 1.0000x reference)
#include <cuda_runtime.h>
#include <cstdint>

#define B 16
#define I 256
#define T 8192
#define NSTEP 8189   // T-3 sampled steps
#define TOUT  8190   // T-2 output length

#define BPC 8                 // batches per chain (2 chains)
#define ROWS_PC (BPC * I)     // rows per chain = 2048
#define NCHUNK 256            // 32-step chunks per batch

// Scratch (static __device__ arrays; no allocation anywhere)
__device__ unsigned char g_nsp[B * T];        // [b][t]: bits0-1 = normal, bit2 = special-1
__device__ unsigned char g_delta[B * T];      // [b][jo]: gather delta in {0,1,2}
__device__ uint32_t      g_cmap[B * NCHUNK];  // [b][chunk]: 32-step class map

// ---------------- Threefry-2x32 (JAX-exact) ----------------
__device__ __forceinline__ void tf2x32(uint32_t k1, uint32_t k2,
                                       uint32_t c0, uint32_t c1,
                                       uint32_t& o0, uint32_t& o1) {
    uint32_t ks2 = k1 ^ k2 ^ 0x1BD11BDAu;
    uint32_t x0 = c0 + k1;
    uint32_t x1 = c1 + k2;
#define TFR(r) { x0 += x1; x1 = __funnelshift_l(x1, x1, (r)); x1 ^= x0; }
    TFR(13) TFR(15) TFR(26) TFR(6)
    x0 += k2;  x1 += ks2 + 1u;
    TFR(17) TFR(29) TFR(16) TFR(24)
    x0 += ks2; x1 += k1 + 2u;
    TFR(13) TFR(15) TFR(26) TFR(6)
    x0 += k1;  x1 += k2 + 3u;
    TFR(17) TFR(29) TFR(16) TFR(24)
    x0 += k2;  x1 += ks2 + 4u;
    TFR(13) TFR(15) TFR(26) TFR(6)
    x0 += ks2; x1 += k1 + 5u;
#undef TFR
    o0 = x0; o1 = x1;
}

// gumbel from 32 random bits, replicating jax._src.random._uniform + gumbel
__device__ __forceinline__ float gumbel_bits(uint32_t bits) {
    const float TINY = 1.17549435e-38f;   // finfo(float32).tiny
    float f = __uint_as_float((bits >> 9) | 0x3F800000u) - 1.0f;  // [0,1)
    float u = fmaxf(TINY, f + TINY);
    return -logf(-logf(u));
}

// ---------------- Class-domain FSM machinery ----------------
// State v = 3*p2+p1 in [0,9); class(v): v==5 -> 3, else v%3.
// Key identity: v % 3 == min(class(v), 2)  -> choices recoverable from class.
// A map = 4 bytes, byte c = class reached starting from class c (values 0..3).

// compose: apply p then c. result byte i = c[p[i]]. PRMT-based.
__device__ __forceinline__ uint32_t compose(uint32_t p, uint32_t c) {
    uint32_t u   = (p | (p >> 4)) & 0x00FF00FFu;   // byte0=p0|p1<<4, byte2=p2|p3<<4
    uint32_t sel = u | (u >> 8);                   // nibbles [p0,p1,p2,p3]
    return __byte_perm(c, 0u, sel);
}

// single-step class map from an nsp byte.
// classes (0,1,2,3) step to classes (n, n+(n==2), n, sp).
__device__ __forceinline__ uint32_t stepmap(uint32_t byt) {
    uint32_t n   = byt & 3u;
    uint32_t is2 = (n == 2u) ? 1u : 0u;
    uint32_t sp  = 1u + ((byt >> 2) & 1u);
    return n * 0x00010101u + (is2 << 8) + (sp << 24);
}

// ---------------- Kernel 1: draws + chunk maps for one chain ----------------
// 256 threads = 32 t x 8 b -> warp w holds batch w's 32 consecutive steps,
// one per lane. After the draws, a 5-level warp scan composes the block's
// 32-step chunk map for each batch (nearly free, hidden under kgen latency).
__global__ __launch_bounds__(256) void kgen(const int* __restrict__ seedp, int b0) {
    __shared__ uint2 skey[32];

    int tid  = threadIdx.x;
    int lane = tid & 31;                // = t within chunk
    int b    = b0 + (tid >> 5);         // warp = batch
    int t    = blockIdx.x * 32 + lane;

    uint32_t seed_lo = (uint32_t)(*seedp);  // threefry_seed: k1 = seed>>32 = 0

    if (tid < 32) {
        uint32_t kx, ky;
        tf2x32(0u, seed_lo, 0u, (uint32_t)(blockIdx.x * 32 + tid), kx, ky);
        skey[tid] = make_uint2(kx, ky);
    }
    __syncthreads();

    uint32_t byt = 0u;                  // t >= NSTEP: deterministic 0
    if (t < NSTEP) {
        uint2 key = skey[lane];
        // three independent threefries (compiler interleaves -> 3-way ILP)
        uint32_t a0, a1, d0, d1, c0_, c1_;
        tf2x32(key.x, key.y, 0u, (uint32_t)(b * 3 + 0), a0, a1);
        tf2x32(key.x, key.y, 0u, (uint32_t)(b * 3 + 1), d0, d1);
        tf2x32(key.x, key.y, 0u, (uint32_t)(b * 3 + 2), c0_, c1_);
        float g0 = gumbel_bits(a0 ^ a1);
        float g1 = gumbel_bits(d0 ^ d1);
        float g2 = gumbel_bits(c0_ ^ c1_);

        const double pd = 0.1, sd = 1.0 - 2.0 * 0.1;
        float lp  = logf(0.1f);
        float ls  = logf(0.8f);
        float l1s = logf((float)(sd / (pd + sd)));  // special row k=1
        float l2s = logf((float)(pd / (pd + sd)));  // special row k=2 (k=0 -inf)

        // normal row argmax (first max wins)
        float v0 = g0 + lp, v1 = g1 + ls, v2 = g2 + lp;
        int n = 0; float best = v0;
        if (v1 > best) { best = v1; n = 1; }
        if (v2 > best) { n = 2; }

        // special row argmax over {1,2}
        int sp = (g2 + l2s > g1 + l1s) ? 2 : 1;

        byt = (uint32_t)(n | ((sp - 1) << 2));
    }
    g_nsp[b * T + t] = (unsigned char)byt;

    // 32-step chunk map via warp-scan composition (lane order = t order)
    uint32_t m = stepmap(byt);
#pragma unroll
    for (int off = 1; off < 32; off <<= 1) {
        uint32_t p = __shfl_up_sync(0xFFFFFFFFu, m, off);
        if (lane >= off) m = compose(p, m);
    }
    if (lane == 31) g_cmap[b * NCHUNK + blockIdx.x] = m;
}

// ---------------- Kernel 2: light scan + emit, 1 block/batch ----------------
// 1024 threads. Threads 0..255 scan the 256 precomposed chunk maps (5 shfl
// levels + small cross-warp combine, 2 barriers). All threads build their
// local 8-step map + 2-level mini-scan within 4-thread groups, then emit 8
// delta bytes as one aligned STG.64.
__global__ __launch_bounds__(1024) void kscan(int b0) {
    int b    = b0 + blockIdx.x;
    int j    = threadIdx.x;            // 0..1023; chunk c = j>>2, sub = j&3
    int lane = j & 31;
    int c    = j >> 2;
    int sub  = j & 3;
    __shared__ uint32_t spfx[NCHUNK];  // inclusive chunk-prefix maps
    __shared__ uint32_t wt8[8];

    // local 8-step maps (independent of chunk-map scan)
    uint2 wv = __ldg(reinterpret_cast<const uint2*>(g_nsp + b * T + j * 8));
    uint32_t w[2] = {wv.x, wv.y};
    uint32_t cm[7];
    cm[0] = stepmap(w[0] & 0xFFu);
#pragma unroll
    for (int s = 1; s < 7; s++)
        cm[s] = compose(cm[s - 1], stepmap((w[s >> 2] >> ((s & 3) * 8)) & 0xFFu));
    uint32_t m8 = compose(cm[6], stepmap(w[1] >> 24));

    // mini inclusive scan of m8 within each 4-thread group
    uint32_t g4 = m8;
#pragma unroll
    for (int off = 1; off < 4; off <<= 1) {
        uint32_t p = __shfl_up_sync(0xFFFFFFFFu, g4, off);
        if ((lane & 3) >= off) g4 = compose(p, g4);
    }
    uint32_t excl4 = __shfl_up_sync(0xFFFFFFFFu, g4, 1);  // valid when sub>0

    // stage A: threads 0..255 scan the chunk maps
    if (j < NCHUNK) {
        uint32_t cmv = g_cmap[b * NCHUNK + j];
#pragma unroll
        for (int off = 1; off < 32; off <<= 1) {
            uint32_t p = __shfl_up_sync(0xFFFFFFFFu, cmv, off);
            if (lane >= off) cmv = compose(p, cmv);
        }
        spfx[j] = cmv;                 // intra-warp inclusive
        if (lane == 31) wt8[j >> 5] = cmv;
    }
    __syncthreads();
    if (j < NCHUNK) {
        int wrp = j >> 5;
        if (wrp > 0) {
            uint32_t acc = wt8[0];
            for (int k = 1; k < wrp; k++) acc = compose(acc, wt8[k]);
            spfx[j] = compose(acc, spfx[j]);
        }
    }
    __syncthreads();

    // entry class: chunk entry from prefix map (init state 4 = class 1 ->
    // byte1), then local sub-prefix within the chunk.
    uint32_t clc = (c == 0) ? 1u : ((spfx[c - 1] >> 8) & 3u);
    uint32_t cl0 = (sub == 0) ? clc : ((excl4 >> (8u * clc)) & 3u);

    // emit: byte0 = min(cl0,2) (prev step's choice / fixed delta[0]=1),
    // bytes 1..7 = choices of this group's first 7 steps.
    uint32_t m0 = (cl0 == 3u) ? 2u : cl0;
    uint32_t lo = m0, hi = 0;
#pragma unroll
    for (int s = 0; s < 7; s++) {
        uint32_t cls = (s == 0) ? cl0 : ((cm[s - 1] >> (8u * cl0)) & 3u);
        uint32_t byt = (w[s >> 2] >> ((s & 3) * 8)) & 0xFFu;
        uint32_t n = byt & 3u, sp = 1u + ((byt >> 2) & 1u);
        uint32_t ch = (cls == 3u) ? sp : n;
        if (s < 3) lo |= ch << (8 * (s + 1));
        else       hi |= ch << (8 * (s - 3));
    }
    *reinterpret_cast<uint2*>(g_delta + b * T + j * 8) = make_uint2(lo, hi);
}

// ---------------- Kernel 3: barrier-free warp gather, 8 outputs/thread ----
__global__ __launch_bounds__(256) void kgather(const float* __restrict__ x,
                                               float* __restrict__ y, int b0) {
    int gw   = blockIdx.x * 8 + (threadIdx.x >> 5);  // warp id within chain
    int lane = threadIdx.x & 31;
    int row  = b0 * I + (gw >> 5);                   // b*I + i (32 warps/row)
    int wseg = gw & 31;
    int wb   = wseg << 8;                            // warp base within row
    int b    = row >> 8;
    bool last = (wseg == 31);                        // row tail warp

    const float* xr = x + (size_t)row * T + wb;
    float4 a = __ldcs(reinterpret_cast<const float4*>(xr) + lane * 2);
    float4 c = __ldcs(reinterpret_cast<const float4*>(xr) + lane * 2 + 1);
    uint2 dd = *reinterpret_cast<const uint2*>(g_delta + (size_t)b * T + wb + lane * 8);

    float ex0 = 0.f, ex1 = 0.f;
    if (!last && lane == 0) {
        float2 e = __ldg(reinterpret_cast<const float2*>(xr + 256));
        ex0 = e.x; ex1 = e.y;
    }
    ex0 = __shfl_sync(0xFFFFFFFFu, ex0, 0);
    ex1 = __shfl_sync(0xFFFFFFFFu, ex1, 0);

    float nx = __shfl_down_sync(0xFFFFFFFFu, a.x, 1);
    float ny = __shfl_down_sync(0xFFFFFFFFu, a.y, 1);
    if (lane == 31) { nx = ex0; ny = ex1; }

    float rr[10] = {a.x, a.y, a.z, a.w, c.x, c.y, c.z, c.w, nx, ny};
    float o[8];
#pragma unroll
    for (int q = 0; q < 8; q++) {
        uint32_t d = ((q < 4 ? dd.x >> (8 * q) : dd.y >> (8 * (q - 4))) & 3u);
        o[q] = (d == 0) ? rr[q] : ((d == 1) ? rr[q + 1] : rr[q + 2]);
    }

    float* yr = y + (size_t)row * TOUT + wb + lane * 8;
    bool tail = last && (lane == 31);
    if (!tail) {
        if ((row & 1) == 0) {
            __stcs(reinterpret_cast<float4*>(yr),     make_float4(o[0], o[1], o[2], o[3]));
            __stcs(reinterpret_cast<float4*>(yr) + 1, make_float4(o[4], o[5], o[6], o[7]));
        } else {
            __stcs(reinterpret_cast<float2*>(yr),     make_float2(o[0], o[1]));
            __stcs(reinterpret_cast<float2*>(yr) + 1, make_float2(o[2], o[3]));
            __stcs(reinterpret_cast<float2*>(yr) + 2, make_float2(o[4], o[5]));
            __stcs(reinterpret_cast<float2*>(yr) + 3, make_float2(o[6], o[7]));
        }
    } else {
        __stcs(reinterpret_cast<float2*>(yr),     make_float2(o[0], o[1]));
        __stcs(reinterpret_cast<float2*>(yr) + 1, make_float2(o[2], o[3]));
        __stcs(reinterpret_cast<float2*>(yr) + 2, make_float2(o[4], o[5]));
    }
}

// ---------------- One extra stream + 2 events (handles only, no dev mem) ---
struct ChainStreams {
    cudaStream_t s1;
    cudaEvent_t  fork, join;
    ChainStreams() {
        cudaStreamCreateWithFlags(&s1, cudaStreamNonBlocking);
        cudaEventCreateWithFlags(&fork, cudaEventDisableTiming);
        cudaEventCreateWithFlags(&join, cudaEventDisableTiming);
    }
};
static ChainStreams g_cs;

extern "C" void kernel_launch(void* const* d_in, const int* in_sizes, int n_in,
                              void* d_out, int out_size) {
    const float* x   = (const float*)d_in[0];
    const int* seedp = (const int*)d_in[1];
    float* y = (float*)d_out;

    cudaEventRecord(g_cs.fork, 0);
    cudaStreamWaitEvent(g_cs.s1, g_cs.fork, 0);

    // prologues first (adjacent in submission order), then gathers
    kgen<<<NCHUNK, 256, 0, 0>>>(seedp, 0);
    kgen<<<NCHUNK, 256, 0, g_cs.s1>>>(seedp, BPC);
    kscan<<<BPC, 1024, 0, 0>>>(0);
    kscan<<<BPC, 1024, 0, g_cs.s1>>>(BPC);
    kgather<<<(ROWS_PC * 32) / 8, 256, 0, 0>>>(x, y, 0);
    kgather<<<(ROWS_PC * 32) / 8, 256, 0, g_cs.s1>>>(x, y, BPC);

    cudaEventRecord(g_cs.join, g_cs.s1);
    cudaStreamWaitEvent(0, g_cs.join, 0);
}